// round 6
// baseline (speedup 1.0000x reference)
#include <cuda_runtime.h>

#define NN 100000   // nodes
#define EE 500000   // edges
#define ND 16       // node_dim
#define ED 8        // edge_dim
#define HD 16       // hidden_dim
#define NG 32       // graphs

#define CHUNK 512
#define NCHUNK ((NN + CHUNK - 1) / CHUNK)   // 196

// Scratch (no allocation allowed -> __device__ globals)
__device__ __align__(128) float g_v[(size_t)NN * HD * ED];   // 51.2 MB: v[n][d][o]
__device__ __align__(128) float g_bb[(size_t)NN * HD];
__device__ __align__(128) float g_agg1[(size_t)NN * HD];
__device__ __align__(128) float g_agg2[(size_t)NN * HD];
__device__ float g_sums[NG * HD];
__device__ float g_cnts[NG];

// CSR-by-src build scratch
__device__ int g_cnt[NN];
__device__ int g_start[NN];
__device__ int g_cursor[NN];
__device__ int g_order[EE];
__device__ int g_chunksum[NCHUNK];

// ---------------------------------------------------------------------------
// Counting sort of edge ids by src node (locality for the v gather).
// ---------------------------------------------------------------------------
__global__ void k_zero_cnt()
{
    int i = blockIdx.x * 256 + threadIdx.x;
    if (i < NN) g_cnt[i] = 0;
}

__global__ void k_count(const int* __restrict__ ei)
{
    int e = blockIdx.x * 256 + threadIdx.x;
    if (e < EE) atomicAdd(&g_cnt[__ldg(ei + e)], 1);
}

__global__ void __launch_bounds__(CHUNK) k_scan1()
{
    __shared__ int s[CHUNK];
    int tid = threadIdx.x;
    int i = blockIdx.x * CHUNK + tid;
    int val = (i < NN) ? g_cnt[i] : 0;
    s[tid] = val;
    __syncthreads();
#pragma unroll
    for (int off = 1; off < CHUNK; off <<= 1) {
        int t = (tid >= off) ? s[tid - off] : 0;
        __syncthreads();
        s[tid] += t;
        __syncthreads();
    }
    if (i < NN) g_start[i] = s[tid] - val;          // local exclusive
    if (tid == CHUNK - 1) g_chunksum[blockIdx.x] = s[tid];
}

__global__ void __launch_bounds__(256) k_scan2()
{
    __shared__ int s[256];
    int tid = threadIdx.x;
    int val = (tid < NCHUNK) ? g_chunksum[tid] : 0;
    s[tid] = val;
    __syncthreads();
#pragma unroll
    for (int off = 1; off < 256; off <<= 1) {
        int t = (tid >= off) ? s[tid - off] : 0;
        __syncthreads();
        s[tid] += t;
        __syncthreads();
    }
    if (tid < NCHUNK) g_chunksum[tid] = s[tid] - val;  // exclusive
}

__global__ void k_scan3()
{
    int i = blockIdx.x * 256 + threadIdx.x;
    if (i < NN) {
        int st = g_start[i] + g_chunksum[i / CHUNK];
        g_start[i] = st;
        g_cursor[i] = st;
    }
}

__global__ void k_scatter(const int* __restrict__ ei)
{
    int e = blockIdx.x * 256 + threadIdx.x;
    if (e < EE) {
        int pos = atomicAdd(&g_cursor[__ldg(ei + e)], 1);
        g_order[pos] = e;
    }
}

// ---------------------------------------------------------------------------
// Prep v4: 32 nodes/block, 256 threads. Thread (ng=tid>>5, d=(tid>>2)&7,
// q=tid&3) computes v[n][d][q*4..q*4+3] (float4) for 4 nodes, coalesced
// STG.128. Weights staged TRANSPOSED in smem (sW4t[i*32+d*4+q]) so each
// warp's LDS.128 covers 512 contiguous bytes -> conflict-free.
// ---------------------------------------------------------------------------
template <bool RELU_IN, bool ZERO_POOL>
__global__ void __launch_bounds__(256) prep_kernel(
    const float* __restrict__ h, const float* __restrict__ W,
    const float* __restrict__ b, const float* __restrict__ root,
    const float* __restrict__ bias,
    float* __restrict__ v, float* __restrict__ bb, float* __restrict__ agg)
{
    __shared__ float4 sW4[512];                // 8 KB, [i][d][q]
    __shared__ float sR[ND * HD];
    __shared__ float sB[ND * HD];
    __shared__ float sBias[HD];
    __shared__ float sH[32 * 16];              // 2 KB

    int tid = threadIdx.x;
    if (ZERO_POOL && blockIdx.x == 0) {
        for (int i = tid; i < NG * HD; i += 256) g_sums[i] = 0.f;
        if (tid < NG) g_cnts[tid] = 0.f;
    }
    const float4* W4 = reinterpret_cast<const float4*>(W);
    for (int idx = tid; idx < 512; idx += 256) {
        int i = idx >> 5, r = idx & 31;        // r = d*4+q
        sW4[idx] = __ldg(W4 + (r >> 2) * 64 + i * 4 + (r & 3));
    }
    for (int i = tid; i < 256; i += 256) { sR[i] = root[i]; sB[i] = b[i]; }
    if (tid < HD) sBias[tid] = bias[tid];

    int nodeBase = blockIdx.x * 32;
    if (tid < 128) {
        int node = nodeBase + (tid >> 2);
        float4 hv = make_float4(0.f, 0.f, 0.f, 0.f);
        if (node < NN)
            hv = __ldg(reinterpret_cast<const float4*>(h) + (size_t)node * 4 + (tid & 3));
        if (RELU_IN) {
            hv.x = fmaxf(hv.x, 0.f); hv.y = fmaxf(hv.y, 0.f);
            hv.z = fmaxf(hv.z, 0.f); hv.w = fmaxf(hv.w, 0.f);
        }
        reinterpret_cast<float4*>(sH)[tid] = hv;
    }
    __syncthreads();

    int ng = tid >> 5;
    int dq = tid & 31;        // d*4+q
    int d = dq >> 2;
    int q = tid & 3;
    bool isAgg = d < 4;
    int o2 = (d & 3) * 4 + q;

    float4 acc[4];
    float sacc[4];
#pragma unroll
    for (int j = 0; j < 4; j++) {
        acc[j] = make_float4(0.f, 0.f, 0.f, 0.f);
        sacc[j] = isAgg ? sBias[o2] : 0.f;
    }

#pragma unroll
    for (int i = 0; i < 16; i++) {
        float4 wv = sW4[i * 32 + dq];          // conflict-free across warp
        float rb = isAgg ? sR[i * 16 + o2] : sB[i * 16 + o2];
#pragma unroll
        for (int j = 0; j < 4; j++) {
            float hv = sH[(ng * 4 + j) * 16 + i];   // warp-broadcast
            acc[j].x = fmaf(hv, wv.x, acc[j].x);
            acc[j].y = fmaf(hv, wv.y, acc[j].y);
            acc[j].z = fmaf(hv, wv.z, acc[j].z);
            acc[j].w = fmaf(hv, wv.w, acc[j].w);
            sacc[j] = fmaf(hv, rb, sacc[j]);
        }
    }

    float4* vout = reinterpret_cast<float4*>(v) + (size_t)nodeBase * 32;
#pragma unroll
    for (int j = 0; j < 4; j++) {
        int nl = ng * 4 + j;
        int node = nodeBase + nl;
        if (node < NN) {
            vout[nl * 32 + dq] = acc[j];
            if (isAgg) agg[(size_t)node * 16 + o2] = sacc[j];
            else       bb[(size_t)node * 16 + o2] = sacc[j];
        }
    }
}

// ---------------------------------------------------------------------------
// Edge kernel v4: edges visited in src-sorted order via g_order -> v lines
// reused through L1. 8 lanes per edge; lane r reads float4 at byte offset
// l*128 + r*16 of v[src]; partial fired directly as red.global.add.v4.
// ---------------------------------------------------------------------------
__global__ void __launch_bounds__(256) edge_kernel(
    const int* __restrict__ ei, const float* __restrict__ ea,
    const float* __restrict__ v, const float* __restrict__ bb,
    float* __restrict__ agg)
{
    int gid = blockIdx.x * 256 + threadIdx.x;
    int idx = gid >> 3;
    if (idx >= EE) return;
    int e = __ldg(g_order + idx);
    int r = gid & 7;
    int hlf = r >> 2;
    int q = r & 3;

    int src = __ldg(ei + e);
    int dst = __ldg(ei + EE + e);

    const float4* eap = reinterpret_cast<const float4*>(ea + (size_t)e * 8);
    float4 ea0 = __ldg(eap);
    float4 ea1 = __ldg(eap + 1);
    float c0 = hlf ? ea0.y : ea0.x;
    float c1 = hlf ? ea0.w : ea0.z;
    float c2 = hlf ? ea1.y : ea1.x;
    float c3 = hlf ? ea1.w : ea1.z;

    const float4* vp = reinterpret_cast<const float4*>(v + (size_t)src * 128) + r;
    float4 v0 = __ldg(vp);
    float4 v1 = __ldg(vp + 8);
    float4 v2 = __ldg(vp + 16);
    float4 v3 = __ldg(vp + 24);

    float ax = fmaf(c0, v0.x, fmaf(c1, v1.x, fmaf(c2, v2.x, c3 * v3.x)));
    float ay = fmaf(c0, v0.y, fmaf(c1, v1.y, fmaf(c2, v2.y, c3 * v3.y)));
    float az = fmaf(c0, v0.z, fmaf(c1, v1.z, fmaf(c2, v2.z, c3 * v3.z)));
    float aw = fmaf(c0, v0.w, fmaf(c1, v1.w, fmaf(c2, v2.w, c3 * v3.w)));

    if (hlf == 0) {
        float4 bbq = __ldg(reinterpret_cast<const float4*>(bb + (size_t)src * 16) + q);
        ax += bbq.x; ay += bbq.y; az += bbq.z; aw += bbq.w;
    }

    float* ap = agg + (size_t)dst * 16 + q * 4;
    asm volatile("red.global.add.v4.f32 [%0], {%1,%2,%3,%4};"
                 :: "l"(ap), "f"(ax), "f"(ay), "f"(az), "f"(aw)
                 : "memory");
}

// ---------------------------------------------------------------------------
// Pooling: batch sorted -> register-accumulate runs, flush on change.
// ---------------------------------------------------------------------------
#define POOL_NODES_PER_HALF 32
__global__ void __launch_bounds__(256) pool_kernel(
    const float* __restrict__ agg, const int* __restrict__ batch)
{
    int gwarp = (blockIdx.x * 256 + threadIdx.x) >> 5;
    int lane = threadIdx.x & 31;
    int o = lane & 15;
    int sub = lane >> 4;
    int base = (gwarp * 2 + sub) * POOL_NODES_PER_HALF;

    float rsum = 0.f, rcnt = 0.f;
    int curg = -1;
#pragma unroll 4
    for (int k = 0; k < POOL_NODES_PER_HALF; k++) {
        int node = base + k;
        if (node >= NN) break;
        int g = __ldg(batch + node);
        if (g != curg) {
            if (curg >= 0) {
                atomicAdd(&g_sums[curg * HD + o], rsum);
                if (o == 0) atomicAdd(&g_cnts[curg], rcnt);
            }
            curg = g; rsum = 0.f; rcnt = 0.f;
        }
        rsum += fmaxf(__ldg(agg + (size_t)node * 16 + o), 0.f);
        rcnt += 1.f;
    }
    if (curg >= 0) {
        atomicAdd(&g_sums[curg * HD + o], rsum);
        if (o == 0) atomicAdd(&g_cnts[curg], rcnt);
    }
}

__global__ void final_kernel(float* __restrict__ out)
{
    int t = threadIdx.x;
    if (t < NG * HD) {
        float c = g_cnts[t >> 4];
        out[t] = g_sums[t] / fmaxf(c, 1.f);
    }
}

// ---------------------------------------------------------------------------
// Launch
// ---------------------------------------------------------------------------
extern "C" void kernel_launch(void* const* d_in, const int* in_sizes, int n_in,
                              void* d_out, int out_size)
{
    const float* x     = (const float*)d_in[0];
    const float* ea    = (const float*)d_in[1];
    const float* W1    = (const float*)d_in[2];
    const float* b1    = (const float*)d_in[3];
    const float* root1 = (const float*)d_in[4];
    const float* bias1 = (const float*)d_in[5];
    const float* W2    = (const float*)d_in[6];
    const float* b2    = (const float*)d_in[7];
    const float* root2 = (const float*)d_in[8];
    const float* bias2 = (const float*)d_in[9];
    const int*   ei    = (const int*)d_in[10];
    const int*   batch = (const int*)d_in[11];
    float* out = (float*)d_out;

    float *v, *bb, *agg1, *agg2;
    cudaGetSymbolAddress((void**)&v, g_v);
    cudaGetSymbolAddress((void**)&bb, g_bb);
    cudaGetSymbolAddress((void**)&agg1, g_agg1);
    cudaGetSymbolAddress((void**)&agg2, g_agg2);

    const int nodes_grid = (NN + 255) / 256;
    const int edges_grid = (EE + 255) / 256;
    const int prep_grid = (NN + 31) / 32;
    const int edge_grid = (EE * 8 + 255) / 256;
    const int pool_halves = (NN + POOL_NODES_PER_HALF - 1) / POOL_NODES_PER_HALF;
    const int pool_grid = (pool_halves / 2 + 7) / 8 + 1;

    // build src-sorted edge order (counting sort)
    k_zero_cnt<<<nodes_grid, 256>>>();
    k_count<<<edges_grid, 256>>>(ei);
    k_scan1<<<NCHUNK, CHUNK>>>();
    k_scan2<<<1, 256>>>();
    k_scan3<<<nodes_grid, 256>>>();
    k_scatter<<<edges_grid, 256>>>(ei);

    prep_kernel<false, true><<<prep_grid, 256>>>(x, W1, b1, root1, bias1, v, bb, agg1);
    edge_kernel<<<edge_grid, 256>>>(ei, ea, v, bb, agg1);
    prep_kernel<true, false><<<prep_grid, 256>>>(agg1, W2, b2, root2, bias2, v, bb, agg2);
    edge_kernel<<<edge_grid, 256>>>(ei, ea, v, bb, agg2);
    pool_kernel<<<pool_grid, 256>>>(agg2, batch);
    final_kernel<<<1, 512>>>(out);
}

// round 7
// speedup vs baseline: 1.2623x; 1.2623x over previous
#include <cuda_runtime.h>

#define NN 100000   // nodes
#define EE 500000   // edges
#define ND 16       // node_dim
#define ED 8        // edge_dim
#define HD 16       // hidden_dim
#define NG 32       // graphs

// Scratch (no allocation allowed -> __device__ globals)
__device__ __align__(128) float g_v[(size_t)NN * HD * ED];   // 51.2 MB: v[n][d][o]
__device__ __align__(128) float g_bb[(size_t)NN * HD];
__device__ __align__(128) float g_agg1[(size_t)NN * HD];
__device__ __align__(128) float g_agg2[(size_t)NN * HD];
__device__ float g_sums[NG * HD];
__device__ float g_cnts[NG];

// ---------------------------------------------------------------------------
// Prep v4: 32 nodes/block, 256 threads. Thread (ng=tid>>5, dq=tid&31,
// d=dq>>2, q=tid&3) computes v[n][d][q*4..q*4+3] (float4) for 4 nodes,
// fully-coalesced STG.128. Weights staged TRANSPOSED in smem
// (sW4[i*32 + dq]) so each warp's LDS.128 covers 512 contiguous bytes ->
// conflict-free (the [d][i][q] layout had a 1024B stride = same banks).
// Threads d<4 compute agg[n][o2], d>=4 compute bb[n][o2], o2=(d&3)*4+q.
// ---------------------------------------------------------------------------
template <bool RELU_IN, bool ZERO_POOL>
__global__ void __launch_bounds__(256) prep_kernel(
    const float* __restrict__ h, const float* __restrict__ W,
    const float* __restrict__ b, const float* __restrict__ root,
    const float* __restrict__ bias,
    float* __restrict__ v, float* __restrict__ bb, float* __restrict__ agg)
{
    __shared__ float4 sW4[512];                // 8 KB, [i][d][q]
    __shared__ float sR[ND * HD];
    __shared__ float sB[ND * HD];
    __shared__ float sBias[HD];
    __shared__ float sH[32 * 16];              // 2 KB

    int tid = threadIdx.x;
    if (ZERO_POOL && blockIdx.x == 0) {
        for (int i = tid; i < NG * HD; i += 256) g_sums[i] = 0.f;
        if (tid < NG) g_cnts[tid] = 0.f;
    }
    const float4* W4 = reinterpret_cast<const float4*>(W);
    for (int idx = tid; idx < 512; idx += 256) {
        int i = idx >> 5, r = idx & 31;        // r = d*4+q
        sW4[idx] = __ldg(W4 + (r >> 2) * 64 + i * 4 + (r & 3));
    }
    for (int i = tid; i < 256; i += 256) { sR[i] = root[i]; sB[i] = b[i]; }
    if (tid < HD) sBias[tid] = bias[tid];

    int nodeBase = blockIdx.x * 32;
    if (tid < 128) {
        int node = nodeBase + (tid >> 2);
        float4 hv = make_float4(0.f, 0.f, 0.f, 0.f);
        if (node < NN)
            hv = __ldg(reinterpret_cast<const float4*>(h) + (size_t)node * 4 + (tid & 3));
        if (RELU_IN) {
            hv.x = fmaxf(hv.x, 0.f); hv.y = fmaxf(hv.y, 0.f);
            hv.z = fmaxf(hv.z, 0.f); hv.w = fmaxf(hv.w, 0.f);
        }
        reinterpret_cast<float4*>(sH)[tid] = hv;
    }
    __syncthreads();

    int ng = tid >> 5;
    int dq = tid & 31;        // d*4+q
    int d = dq >> 2;
    int q = tid & 3;
    bool isAgg = d < 4;
    int o2 = (d & 3) * 4 + q;

    float4 acc[4];
    float sacc[4];
#pragma unroll
    for (int j = 0; j < 4; j++) {
        acc[j] = make_float4(0.f, 0.f, 0.f, 0.f);
        sacc[j] = isAgg ? sBias[o2] : 0.f;
    }

#pragma unroll
    for (int i = 0; i < 16; i++) {
        float4 wv = sW4[i * 32 + dq];          // conflict-free across warp
        float rb = isAgg ? sR[i * 16 + o2] : sB[i * 16 + o2];
#pragma unroll
        for (int j = 0; j < 4; j++) {
            float hv = sH[(ng * 4 + j) * 16 + i];   // warp-broadcast
            acc[j].x = fmaf(hv, wv.x, acc[j].x);
            acc[j].y = fmaf(hv, wv.y, acc[j].y);
            acc[j].z = fmaf(hv, wv.z, acc[j].z);
            acc[j].w = fmaf(hv, wv.w, acc[j].w);
            sacc[j] = fmaf(hv, rb, sacc[j]);
        }
    }

    float4* vout = reinterpret_cast<float4*>(v) + (size_t)nodeBase * 32;
#pragma unroll
    for (int j = 0; j < 4; j++) {
        int nl = ng * 4 + j;
        int node = nodeBase + nl;
        if (node < NN) {
            vout[nl * 32 + dq] = acc[j];           // 512B/node coalesced
            if (isAgg) agg[(size_t)node * 16 + o2] = sacc[j];
            else       bb[(size_t)node * 16 + o2] = sacc[j];
        }
    }
}

// ---------------------------------------------------------------------------
// Edge kernel (round-5 version, natural edge order): 8 lanes per edge.
// Lane r reads float4 at byte offset l*128 + r*16 of v[src] (full 128B
// lines). Lane r holds d = 2l + (r>>2), o-quad q = r&3. Each lane fires its
// partial directly as red.global.add.v4; hlf==0 lanes fold in bb.
// ---------------------------------------------------------------------------
__global__ void __launch_bounds__(256) edge_kernel(
    const int* __restrict__ ei, const float* __restrict__ ea,
    const float* __restrict__ v, const float* __restrict__ bb,
    float* __restrict__ agg)
{
    int gid = blockIdx.x * 256 + threadIdx.x;
    int e = gid >> 3;
    if (e >= EE) return;
    int r = gid & 7;
    int hlf = r >> 2;     // 0: even d, 1: odd d
    int q = r & 3;        // output quad

    int src = __ldg(ei + e);
    int dst = __ldg(ei + EE + e);

    const float4* eap = reinterpret_cast<const float4*>(ea + (size_t)e * 8);
    float4 ea0 = __ldg(eap);
    float4 ea1 = __ldg(eap + 1);
    float c0 = hlf ? ea0.y : ea0.x;
    float c1 = hlf ? ea0.w : ea0.z;
    float c2 = hlf ? ea1.y : ea1.x;
    float c3 = hlf ? ea1.w : ea1.z;

    const float4* vp = reinterpret_cast<const float4*>(v + (size_t)src * 128) + r;
    float4 v0 = __ldg(vp);        // d = hlf
    float4 v1 = __ldg(vp + 8);    // d = 2 + hlf
    float4 v2 = __ldg(vp + 16);   // d = 4 + hlf
    float4 v3 = __ldg(vp + 24);   // d = 6 + hlf

    float ax = fmaf(c0, v0.x, fmaf(c1, v1.x, fmaf(c2, v2.x, c3 * v3.x)));
    float ay = fmaf(c0, v0.y, fmaf(c1, v1.y, fmaf(c2, v2.y, c3 * v3.y)));
    float az = fmaf(c0, v0.z, fmaf(c1, v1.z, fmaf(c2, v2.z, c3 * v3.z)));
    float aw = fmaf(c0, v0.w, fmaf(c1, v1.w, fmaf(c2, v2.w, c3 * v3.w)));

    if (hlf == 0) {
        float4 bbq = __ldg(reinterpret_cast<const float4*>(bb + (size_t)src * 16) + q);
        ax += bbq.x; ay += bbq.y; az += bbq.z; aw += bbq.w;
    }

    float* ap = agg + (size_t)dst * 16 + q * 4;
    asm volatile("red.global.add.v4.f32 [%0], {%1,%2,%3,%4};"
                 :: "l"(ap), "f"(ax), "f"(ay), "f"(az), "f"(aw)
                 : "memory");
}

// ---------------------------------------------------------------------------
// Pooling: batch sorted -> register-accumulate runs, flush on change.
// ---------------------------------------------------------------------------
#define POOL_NODES_PER_HALF 32
__global__ void __launch_bounds__(256) pool_kernel(
    const float* __restrict__ agg, const int* __restrict__ batch)
{
    int gwarp = (blockIdx.x * 256 + threadIdx.x) >> 5;
    int lane = threadIdx.x & 31;
    int o = lane & 15;
    int sub = lane >> 4;
    int base = (gwarp * 2 + sub) * POOL_NODES_PER_HALF;

    float rsum = 0.f, rcnt = 0.f;
    int curg = -1;
#pragma unroll 4
    for (int k = 0; k < POOL_NODES_PER_HALF; k++) {
        int node = base + k;
        if (node >= NN) break;
        int g = __ldg(batch + node);
        if (g != curg) {
            if (curg >= 0) {
                atomicAdd(&g_sums[curg * HD + o], rsum);
                if (o == 0) atomicAdd(&g_cnts[curg], rcnt);
            }
            curg = g; rsum = 0.f; rcnt = 0.f;
        }
        rsum += fmaxf(__ldg(agg + (size_t)node * 16 + o), 0.f);
        rcnt += 1.f;
    }
    if (curg >= 0) {
        atomicAdd(&g_sums[curg * HD + o], rsum);
        if (o == 0) atomicAdd(&g_cnts[curg], rcnt);
    }
}

__global__ void final_kernel(float* __restrict__ out)
{
    int t = threadIdx.x;
    if (t < NG * HD) {
        float c = g_cnts[t >> 4];
        out[t] = g_sums[t] / fmaxf(c, 1.f);
    }
}

// ---------------------------------------------------------------------------
// Launch
// ---------------------------------------------------------------------------
extern "C" void kernel_launch(void* const* d_in, const int* in_sizes, int n_in,
                              void* d_out, int out_size)
{
    const float* x     = (const float*)d_in[0];
    const float* ea    = (const float*)d_in[1];
    const float* W1    = (const float*)d_in[2];
    const float* b1    = (const float*)d_in[3];
    const float* root1 = (const float*)d_in[4];
    const float* bias1 = (const float*)d_in[5];
    const float* W2    = (const float*)d_in[6];
    const float* b2    = (const float*)d_in[7];
    const float* root2 = (const float*)d_in[8];
    const float* bias2 = (const float*)d_in[9];
    const int*   ei    = (const int*)d_in[10];
    const int*   batch = (const int*)d_in[11];
    float* out = (float*)d_out;

    float *v, *bb, *agg1, *agg2;
    cudaGetSymbolAddress((void**)&v, g_v);
    cudaGetSymbolAddress((void**)&bb, g_bb);
    cudaGetSymbolAddress((void**)&agg1, g_agg1);
    cudaGetSymbolAddress((void**)&agg2, g_agg2);

    const int prep_grid = (NN + 31) / 32;
    const int edge_grid = (EE * 8 + 255) / 256;
    const int pool_halves = (NN + POOL_NODES_PER_HALF - 1) / POOL_NODES_PER_HALF;
    const int pool_grid = (pool_halves / 2 + 7) / 8 + 1;

    prep_kernel<false, true><<<prep_grid, 256>>>(x, W1, b1, root1, bias1, v, bb, agg1);
    edge_kernel<<<edge_grid, 256>>>(ei, ea, v, bb, agg1);
    prep_kernel<true, false><<<prep_grid, 256>>>(agg1, W2, b2, root2, bias2, v, bb, agg2);
    edge_kernel<<<edge_grid, 256>>>(ei, ea, v, bb, agg2);
    pool_kernel<<<pool_grid, 256>>>(agg2, batch);
    final_kernel<<<1, 512>>>(out);
}